// round 1
// baseline (speedup 1.0000x reference)
#include <cuda_runtime.h>
#include <math.h>

#define T_STEPS 512
#define BATCH   1024
#define HID     64
#define G4      256          // 4*H gate columns
#define B_TILE  8
#define NTHREADS 256

// Inter-layer scratch (allocation-free rule: __device__ globals)
__device__ float g_buf0[BATCH * T_STEPS * HID];   // 128 MB
__device__ float g_buf1[BATCH * T_STEPS * HID];   // 128 MB
__device__ float g_hlast[BATCH * HID];

__device__ __forceinline__ float sigf(float x) {
    return 1.0f / (1.0f + __expf(-x));
}
__device__ __forceinline__ float tanh_fast(float x) {
    float t = fabsf(x);
    float e = __expf(-2.0f * t);
    float r = (1.0f - e) / (1.0f + e);
    return copysignf(r, x);
}

// One CTA = 8 batch elements. Thread t: unit u = t>>2 (0..63), bq = t&3 -> batches bq*2, bq*2+1.
// Smem: W_s[k][unit*4+gate] (k in [0,IN_W) = w_ih cols, [IN_W,IN_W+64) = w_hh cols),
//       xh_s[k][8] (x_t rows then h rows), bias_s[unit*4+gate].
template <int IN_W, bool LAST_ONLY>
__global__ void __launch_bounds__(NTHREADS)
lstm_layer(const float* __restrict__ x,     // [B][T][IN_W]
           const float* __restrict__ w_ih,  // [256][IN_W]
           const float* __restrict__ w_hh,  // [256][64]
           const float* __restrict__ b_ih,  // [256]
           const float* __restrict__ b_hh,  // [256]
           float* __restrict__ y)           // [B][T][64] or [B][64] if LAST_ONLY
{
    constexpr int K = IN_W + HID;
    extern __shared__ float smem[];
    float* W_s    = smem;                       // K * 256
    float* xh_s   = W_s + K * G4;               // K * 8
    float* bias_s = xh_s + K * B_TILE;          // 256

    const int tid = threadIdx.x;
    const int b0  = blockIdx.x * B_TILE;
    const int u   = tid >> 2;
    const int bq  = tid & 3;

    // ---- cooperative weight load + reorder ----
    for (int idx = tid; idx < K * G4; idx += NTHREADS) {
        int k  = idx / G4;
        int cp = idx % G4;            // unit*4 + gate
        int un = cp >> 2, gt = cp & 3;
        int r  = gt * HID + un;       // original row: gate-major
        W_s[idx] = (k < IN_W) ? w_ih[r * IN_W + k]
                              : w_hh[r * HID + (k - IN_W)];
    }
    for (int idx = tid; idx < G4; idx += NTHREADS) {
        int un = idx >> 2, gt = idx & 3;
        int r  = gt * HID + un;
        bias_s[idx] = b_ih[r] + b_hh[r];
    }
    // h_{-1} = 0
    for (int idx = tid; idx < HID * B_TILE; idx += NTHREADS)
        xh_s[IN_W * B_TILE + idx] = 0.0f;
    // x_0
    for (int v = tid; v < IN_W * B_TILE; v += NTHREADS) {
        int b = v / IN_W, k = v % IN_W;
        xh_s[k * B_TILE + b] = x[((size_t)(b0 + b) * T_STEPS + 0) * IN_W + k];
    }
    float c0 = 0.0f, c1 = 0.0f;
    __syncthreads();

    const float4* W4  = (const float4*)W_s;    // [K][64]
    const float2* XH2 = (const float2*)xh_s;   // [K][4]
    const float4  bz  = ((const float4*)bias_s)[u];  // (i,f,g,o) bias for unit u

    for (int t = 0; t < T_STEPS; t++) {
        float a00 = bz.x, a01 = bz.y, a02 = bz.z, a03 = bz.w;
        float a10 = bz.x, a11 = bz.y, a12 = bz.z, a13 = bz.w;
#pragma unroll 8
        for (int k = 0; k < K; k++) {
            float4 w = W4[k * 64 + u];
            float2 a = XH2[k * 4 + bq];
            a00 += a.x * w.x; a01 += a.x * w.y; a02 += a.x * w.z; a03 += a.x * w.w;
            a10 += a.y * w.x; a11 += a.y * w.y; a12 += a.y * w.z; a13 += a.y * w.w;
        }
        float i0 = sigf(a00), f0 = sigf(a01), g0 = tanh_fast(a02), o0 = sigf(a03);
        float i1 = sigf(a10), f1 = sigf(a11), g1 = tanh_fast(a12), o1 = sigf(a13);
        c0 = f0 * c0 + i0 * g0;
        c1 = f1 * c1 + i1 * g1;
        float h0 = o0 * tanh_fast(c0);
        float h1 = o1 * tanh_fast(c1);

        __syncthreads();   // all reads of xh_s for this step are done

        xh_s[(IN_W + u) * B_TILE + bq * 2 + 0] = h0;
        xh_s[(IN_W + u) * B_TILE + bq * 2 + 1] = h1;

        if (!LAST_ONLY) {
            y[((size_t)(b0 + bq * 2 + 0) * T_STEPS + t) * HID + u] = h0;
            y[((size_t)(b0 + bq * 2 + 1) * T_STEPS + t) * HID + u] = h1;
        } else if (t == T_STEPS - 1) {
            y[(size_t)(b0 + bq * 2 + 0) * HID + u] = h0;
            y[(size_t)(b0 + bq * 2 + 1) * HID + u] = h1;
        }

        if (t + 1 < T_STEPS) {
            for (int v = tid; v < IN_W * B_TILE; v += NTHREADS) {
                int b, k;
                if (IN_W == 64) { b = v >> 6; k = v & 63; }
                else           { b = v / IN_W; k = v % IN_W; }
                xh_s[k * B_TILE + b] =
                    x[((size_t)(b0 + b) * T_STEPS + (t + 1)) * IN_W + k];
            }
        }
        __syncthreads();   // new xh ready
    }
}

// MLP head: z = relu(h@fc1^T+b1); z = relu(z@fc3^T+b3); out = z@fc2^T+b2
__global__ void __launch_bounds__(NTHREADS)
head_kernel(const float* __restrict__ hlast,
            const float* __restrict__ fc1_w, const float* __restrict__ fc1_b,
            const float* __restrict__ fc3_w, const float* __restrict__ fc3_b,
            const float* __restrict__ fc2_w, const float* __restrict__ fc2_b,
            float* __restrict__ out)
{
    __shared__ float h_s[8][64];
    __shared__ float z1_s[8][128];
    __shared__ float z2_s[8][64];
    const int tid = threadIdx.x;
    const int b0  = blockIdx.x * 8;

    for (int v = tid; v < 8 * 64; v += NTHREADS)
        h_s[v >> 6][v & 63] = hlast[(size_t)(b0 + (v >> 6)) * 64 + (v & 63)];
    __syncthreads();

    for (int v = tid; v < 8 * 128; v += NTHREADS) {
        int b = v >> 7, j = v & 127;
        float s = fc1_b[j];
#pragma unroll 8
        for (int k = 0; k < 64; k++) s += h_s[b][k] * fc1_w[j * 64 + k];
        z1_s[b][j] = fmaxf(s, 0.0f);
    }
    __syncthreads();

    for (int v = tid; v < 8 * 64; v += NTHREADS) {
        int b = v >> 6, j = v & 63;
        float s = fc3_b[j];
#pragma unroll 8
        for (int k = 0; k < 128; k++) s += z1_s[b][k] * fc3_w[j * 128 + k];
        z2_s[b][j] = fmaxf(s, 0.0f);
    }
    __syncthreads();

    if (tid < 16) {
        int b = tid >> 1, j = tid & 1;
        float s = fc2_b[j];
#pragma unroll
        for (int k = 0; k < 64; k++) s += z2_s[b][k] * fc2_w[j * 64 + k];
        out[(b0 + b) * 2 + j] = s;
    }
}

extern "C" void kernel_launch(void* const* d_in, const int* in_sizes, int n_in,
                              void* d_out, int out_size)
{
    const float* x     = (const float*)d_in[0];
    const float* w_ih0 = (const float*)d_in[1];
    const float* w_hh0 = (const float*)d_in[2];
    const float* b_ih0 = (const float*)d_in[3];
    const float* b_hh0 = (const float*)d_in[4];
    const float* w_ih1 = (const float*)d_in[5];
    const float* w_hh1 = (const float*)d_in[6];
    const float* b_ih1 = (const float*)d_in[7];
    const float* b_hh1 = (const float*)d_in[8];
    const float* w_ih2 = (const float*)d_in[9];
    const float* w_hh2 = (const float*)d_in[10];
    const float* b_ih2 = (const float*)d_in[11];
    const float* b_hh2 = (const float*)d_in[12];
    const float* fc1_w = (const float*)d_in[13];
    const float* fc1_b = (const float*)d_in[14];
    const float* fc3_w = (const float*)d_in[15];
    const float* fc3_b = (const float*)d_in[16];
    const float* fc2_w = (const float*)d_in[17];
    const float* fc2_b = (const float*)d_in[18];
    float* out = (float*)d_out;

    float *buf0 = nullptr, *buf1 = nullptr, *hlast = nullptr;
    cudaGetSymbolAddress((void**)&buf0,  g_buf0);
    cudaGetSymbolAddress((void**)&buf1,  g_buf1);
    cudaGetSymbolAddress((void**)&hlast, g_hlast);

    // dynamic smem sizes
    const int SMEM_L0  = (70  * G4 + 70  * B_TILE + G4) * (int)sizeof(float); //  74944
    const int SMEM_L12 = (128 * G4 + 128 * B_TILE + G4) * (int)sizeof(float); // 136192

    cudaFuncSetAttribute((const void*)lstm_layer<6,  false>,
                         cudaFuncAttributeMaxDynamicSharedMemorySize, SMEM_L0);
    cudaFuncSetAttribute((const void*)lstm_layer<64, false>,
                         cudaFuncAttributeMaxDynamicSharedMemorySize, SMEM_L12);
    cudaFuncSetAttribute((const void*)lstm_layer<64, true>,
                         cudaFuncAttributeMaxDynamicSharedMemorySize, SMEM_L12);

    const int GRID = BATCH / B_TILE;   // 128

    lstm_layer<6,  false><<<GRID, NTHREADS, SMEM_L0 >>>(x,    w_ih0, w_hh0, b_ih0, b_hh0, buf0);
    lstm_layer<64, false><<<GRID, NTHREADS, SMEM_L12>>>(buf0, w_ih1, w_hh1, b_ih1, b_hh1, buf1);
    lstm_layer<64, true ><<<GRID, NTHREADS, SMEM_L12>>>(buf1, w_ih2, w_hh2, b_ih2, b_hh2, hlast);
    head_kernel<<<GRID, NTHREADS>>>(hlast, fc1_w, fc1_b, fc3_w, fc3_b, fc2_w, fc2_b, out);
}